// round 11
// baseline (speedup 1.0000x reference)
#include <cuda_runtime.h>
#include <cuda_bf16.h>
#include <cstdint>

// Problem constants (fixed shapes per reference)
#define B_ROWS   4096
#define N_COLS   64
#define BIN      256
#define TOT      (N_COLS * BIN)   // 16384

// Persistent grid: 4 CTAs/SM on 148 SMs.
#define GRID     592

// Pipeline chunking: 8 columns per chunk = 8KB logits + 8KB gumbel.
#define CHUNK_COLS    8
#define CHUNK_FLOATS  (CHUNK_COLS * BIN)   // 2048
#define CHUNK_BYTES   (CHUNK_FLOATS * 4)   // 8192
#define NSTAGES       2

// Scratch: per-block partials + last-block ticket counter (no allocs allowed).
__device__ float g_block_partials[GRID];
__device__ unsigned int g_ticket = 0;   // reset to 0 by the last block each launch

static __device__ __forceinline__ uint32_t smem_u32(const void* p) {
    return (uint32_t)__cvta_generic_to_shared(p);
}

static __device__ __forceinline__ void mbar_init(uint32_t mbar, uint32_t count) {
    asm volatile("mbarrier.init.shared.b64 [%0], %1;" :: "r"(mbar), "r"(count) : "memory");
}

static __device__ __forceinline__ void mbar_expect_tx(uint32_t mbar, uint32_t bytes) {
    asm volatile("mbarrier.arrive.expect_tx.shared.b64 _, [%0], %1;"
                 :: "r"(mbar), "r"(bytes) : "memory");
}

static __device__ __forceinline__ void bulk_g2s(uint32_t dst_smem, const void* src,
                                                uint32_t bytes, uint32_t mbar) {
    asm volatile("cp.async.bulk.shared::cta.global.mbarrier::complete_tx::bytes "
                 "[%0], [%1], %2, [%3];"
                 :: "r"(dst_smem), "l"(src), "r"(bytes), "r"(mbar) : "memory");
}

static __device__ __forceinline__ void mbar_wait(uint32_t mbar, uint32_t parity) {
    uint32_t done;
    asm volatile("{\n\t.reg .pred p;\n\t"
                 "mbarrier.try_wait.parity.acquire.cta.shared::cta.b64 p, [%1], %2;\n\t"
                 "selp.b32 %0, 1, 0, p;\n\t}"
                 : "=r"(done) : "r"(mbar), "r"(parity) : "memory");
    if (!done) {
        asm volatile("{\n\t.reg .pred P1;\n\t"
                     "WL_%=:\n\t"
                     "mbarrier.try_wait.parity.acquire.cta.shared::cta.b64 P1, [%0], %1, 0x989680;\n\t"
                     "@P1 bra.uni WD_%=;\n\t"
                     "bra.uni WL_%=;\n\t"
                     "WD_%=:\n\t}"
                     :: "r"(mbar), "r"(parity) : "memory");
    }
}

// Persistent pipelined kernel. A single elected thread streams 16KB chunks
// (8 columns) into double-buffered smem via cp.async.bulk; 8 warps (one per
// column) compute exp-sums out of smem. Load issue never waits on the
// exp/shfl chain. z[target] is read from smem (no extra global traffic).
// No max-subtraction: z bounded (logits ~N(0,1), gumbel <= ~23), fp32-safe.
__global__ __launch_bounds__(256, 4)
void obs_loss_kernel(const float* __restrict__ logits,
                     const float* __restrict__ gumbel,
                     const int* __restrict__ mask,      // jax bool -> int32
                     const int* __restrict__ targets,
                     float* __restrict__ out)
{
    __shared__ alignas(128) float sL[NSTAGES][CHUNK_FLOATS];
    __shared__ alignas(128) float sG[NSTAGES][CHUNK_FLOATS];
    __shared__ alignas(8)  unsigned long long mbar[NSTAGES];
    __shared__ float sacc[8];
    __shared__ bool  s_last;

    const int tid  = threadIdx.x;
    const int wid  = tid >> 5;
    const int lane = tid & 31;
    const int bid  = blockIdx.x;

    const uint32_t mb[NSTAGES] = { smem_u32(&mbar[0]), smem_u32(&mbar[1]) };

    if (tid == 0) {
        mbar_init(mb[0], 1);
        mbar_init(mb[1], 1);
    }
    __syncthreads();

    const int nrows   = (B_ROWS - 1 - bid) / GRID + 1;
    const int nchunks = nrows * (N_COLS / CHUNK_COLS);   // 8 chunks per row

    // Producer: issue chunk c into stage (c % 2). tid 0 only.
    auto issue = [&](int c) {
        const int stage = c & 1;
        const int row   = bid + (c >> 3) * GRID;
        const size_t off = (size_t)row * TOT + (size_t)(c & 7) * CHUNK_FLOATS;
        mbar_expect_tx(mb[stage], 2 * CHUNK_BYTES);
        bulk_g2s(smem_u32(&sL[stage][0]), logits + off, CHUNK_BYTES, mb[stage]);
        bulk_g2s(smem_u32(&sG[stage][0]), gumbel + off, CHUNK_BYTES, mb[stage]);
    };

    if (tid == 0) {
        issue(0);
        if (nchunks > 1) issue(1);
    }

    int phase0 = 0, phase1 = 0;
    float acc = 0.0f;

    for (int c = 0; c < nchunks; ++c) {
        const int stage = c & 1;
        const int row   = bid + (c >> 3) * GRID;
        const int cc    = (c & 7) * CHUNK_COLS + wid;    // this warp's column

        // Prefetch scattered scalars BEFORE the data wait (latency overlaps).
        int t = 0, mk = 1;
        if (lane == 0) {
            t  = __ldg(&targets[row * N_COLS + cc]);
            mk = __ldg(&mask[(size_t)row * TOT + cc * BIN + t]);
        }

        // Wait for this stage's data.
        const uint32_t m = stage ? mb[1] : mb[0];
        const int      p = stage ? phase1 : phase0;
        mbar_wait(m, p);
        if (stage) phase1 ^= 1; else phase0 ^= 1;

        const float* L = &sL[stage][wid * BIN];
        const float* G = &sG[stage][wid * BIN];

        // Each lane: bins lane*4..+3 and 128+lane*4..+3 (conflict-free v4 LDS).
        float4 a0 = *reinterpret_cast<const float4*>(L + lane * 4);
        float4 a1 = *reinterpret_cast<const float4*>(L + 128 + lane * 4);
        float4 b0 = *reinterpret_cast<const float4*>(G + lane * 4);
        float4 b1 = *reinterpret_cast<const float4*>(G + 128 + lane * 4);

        float s = __expf(a0.x + b0.x) + __expf(a0.y + b0.y)
                + __expf(a0.z + b0.z) + __expf(a0.w + b0.w)
                + __expf(a1.x + b1.x) + __expf(a1.y + b1.y)
                + __expf(a1.z + b1.z) + __expf(a1.w + b1.w);

        #pragma unroll
        for (int off = 16; off > 0; off >>= 1)
            s += __shfl_xor_sync(0xFFFFFFFFu, s, off);

        if (lane == 0 && !mk) {
            const float zt = L[t] + G[t];
            acc += (__logf(s) - zt);     // -(z_t - lse)
        }

        __syncthreads();                 // all warps done reading this stage
        if (tid == 0 && c + NSTAGES < nchunks)
            issue(c + NSTAGES);
    }

    // One block reduce at the very end.
    #pragma unroll
    for (int off = 16; off > 0; off >>= 1)
        acc += __shfl_xor_sync(0xFFFFFFFFu, acc, off);

    if (lane == 0) sacc[wid] = acc;
    __syncthreads();

    if (tid == 0) {
        float s = 0.0f;
        #pragma unroll
        for (int i = 0; i < 8; ++i) s += sacc[i];
        g_block_partials[bid] = s;
        __threadfence();                                   // publish partial
        unsigned int tk = atomicAdd(&g_ticket, 1u);
        s_last = (tk == (unsigned int)(GRID - 1));
    }
    __syncthreads();

    // Last block performs the final deterministic reduction over 592 partials.
    if (s_last) {
        float s = 0.0f;
        for (int i = tid; i < GRID; i += 256)
            s += g_block_partials[i];
        #pragma unroll
        for (int off = 16; off > 0; off >>= 1)
            s += __shfl_xor_sync(0xFFFFFFFFu, s, off);
        if (lane == 0) sacc[wid] = s;
        __syncthreads();
        if (tid == 0) {
            float loss = 0.0f;
            #pragma unroll
            for (int i = 0; i < 8; ++i) loss += sacc[i];
            out[0] = loss;
            out[1] = loss / ((float)B_ROWS * 0.69314718055994530942f);
            g_ticket = 0;                                  // reset for next replay
        }
    }
}

extern "C" void kernel_launch(void* const* d_in, const int* in_sizes, int n_in,
                              void* d_out, int out_size)
{
    const float* logits  = (const float*)d_in[0];
    const float* gumbel  = (const float*)d_in[1];
    const int*   mask    = (const int*)d_in[2];
    const int*   targets = (const int*)d_in[3];
    // d_in[4] = bin_size scalar (256), fixed — unused.
    (void)in_sizes; (void)n_in; (void)out_size;

    obs_loss_kernel<<<GRID, 256>>>(logits, gumbel, mask, targets, (float*)d_out);
}

// round 12
// speedup vs baseline: 1.0851x; 1.0851x over previous
#include <cuda_runtime.h>
#include <cuda_bf16.h>

// Problem constants (fixed shapes per reference)
#define B_ROWS   4096
#define N_COLS   64
#define BIN      256
#define TOT      (N_COLS * BIN)   // 16384

// Persistent grid: 4 CTAs/SM on 148 SMs.
#define GRID     592

// Scratch: per-block partials + last-block ticket counter (no allocs allowed).
__device__ float g_block_partials[GRID];
__device__ unsigned int g_ticket = 0;   // reset to 0 by the last block each launch

static __device__ __forceinline__ void pf_l2(const float* p) {
    asm volatile("prefetch.global.L2 [%0];" :: "l"(p));
}

// Persistent kernel (R9 structure) + L2 prefetch of the NEXT chunk.
// Warp = 4 columns per iteration via 8-lane groups (grp = lane>>3 selects the
// column, sub = lane&7 covers bins sub*4 + k*32). The streaming loop keeps NO
// z values: the target bin's z is re-loaded by the group leader. Each
// iteration, the warp prefetches its next 2x4KB chunk into L2 (one line per
// lane, 2 instructions), so the demand LDGs hit L2 (~240 cyc) instead of
// DRAM (~580 cyc) and MLP=8 sustains a much higher streaming rate.
// No max-subtraction: z bounded (logits ~N(0,1), gumbel <= ~23), fp32-safe.
__global__ __launch_bounds__(256, 4)
void obs_loss_kernel(const float* __restrict__ logits,
                     const float* __restrict__ gumbel,
                     const int* __restrict__ mask,      // jax bool -> int32
                     const int* __restrict__ targets,
                     float* __restrict__ out)
{
    const int wid  = threadIdx.x >> 5;
    const int lane = threadIdx.x & 31;
    const int grp  = lane >> 3;    // which of the warp's 4 columns
    const int sub  = lane & 7;     // position within the 8-lane group

    float acc = 0.0f;   // accumulated across all rows this block handles

    // Prefetch the very first chunk's successor region early.
    {
        const int base0 = (wid * 4) * BIN;
        pf_l2(logits + (size_t)blockIdx.x * TOT + base0 + lane * 32);
        pf_l2(gumbel + (size_t)blockIdx.x * TOT + base0 + lane * 32);
    }

    for (int row = blockIdx.x; row < B_ROWS; row += GRID) {
        const float* lrow = logits + (size_t)row * TOT;
        const float* grow = gumbel + (size_t)row * TOT;

        #pragma unroll
        for (int it = 0; it < 2; ++it) {
            const int mycol = it * 32 + wid * 4 + grp;
            const int cbase = mycol * BIN;

            // ---- Prefetch NEXT chunk (one iteration ahead) into L2.
            {
                int nrow = row, nit = it + 1;
                if (nit == 2) {
                    nit = 0;
                    nrow = row + GRID;
                    if (nrow >= B_ROWS) { nrow = row; nit = it; } // clamp (harmless re-prefetch)
                }
                const int nbase = (nit * 32 + wid * 4) * BIN;
                const float* npl = logits + (size_t)nrow * TOT + nbase + lane * 32;
                const float* npg = gumbel + (size_t)nrow * TOT + nbase + lane * 32;
                pf_l2(npl);
                pf_l2(npg);
            }

            // Group leader prefetches the scattered tail data early so the
            // latency overlaps the streaming loop below.
            int   t_idx = 0, mk = 1;
            float zt = 0.0f;
            if (sub == 0) {
                t_idx = __ldg(&targets[row * N_COLS + mycol]);
                mk    = __ldg(&mask[(size_t)row * TOT + cbase + t_idx]);
                zt    = __ldg(lrow + cbase + t_idx) + __ldg(grow + cbase + t_idx);
            }

            const float* lp = lrow + cbase + sub * 4;
            const float* gp = grow + cbase + sub * 4;

            // ---- Streaming: 8 k-steps, front-batched in two chunks of 4.
            float s = 0.0f;
            {
                float4 a0 = __ldcs(reinterpret_cast<const float4*>(lp + 0 * 32));
                float4 a1 = __ldcs(reinterpret_cast<const float4*>(lp + 1 * 32));
                float4 a2 = __ldcs(reinterpret_cast<const float4*>(lp + 2 * 32));
                float4 a3 = __ldcs(reinterpret_cast<const float4*>(lp + 3 * 32));
                float4 b0 = __ldcs(reinterpret_cast<const float4*>(gp + 0 * 32));
                float4 b1 = __ldcs(reinterpret_cast<const float4*>(gp + 1 * 32));
                float4 b2 = __ldcs(reinterpret_cast<const float4*>(gp + 2 * 32));
                float4 b3 = __ldcs(reinterpret_cast<const float4*>(gp + 3 * 32));
                s += __expf(a0.x + b0.x) + __expf(a0.y + b0.y)
                   + __expf(a0.z + b0.z) + __expf(a0.w + b0.w);
                s += __expf(a1.x + b1.x) + __expf(a1.y + b1.y)
                   + __expf(a1.z + b1.z) + __expf(a1.w + b1.w);
                s += __expf(a2.x + b2.x) + __expf(a2.y + b2.y)
                   + __expf(a2.z + b2.z) + __expf(a2.w + b2.w);
                s += __expf(a3.x + b3.x) + __expf(a3.y + b3.y)
                   + __expf(a3.z + b3.z) + __expf(a3.w + b3.w);
            }
            {
                float4 a0 = __ldcs(reinterpret_cast<const float4*>(lp + 4 * 32));
                float4 a1 = __ldcs(reinterpret_cast<const float4*>(lp + 5 * 32));
                float4 a2 = __ldcs(reinterpret_cast<const float4*>(lp + 6 * 32));
                float4 a3 = __ldcs(reinterpret_cast<const float4*>(lp + 7 * 32));
                float4 b0 = __ldcs(reinterpret_cast<const float4*>(gp + 4 * 32));
                float4 b1 = __ldcs(reinterpret_cast<const float4*>(gp + 5 * 32));
                float4 b2 = __ldcs(reinterpret_cast<const float4*>(gp + 6 * 32));
                float4 b3 = __ldcs(reinterpret_cast<const float4*>(gp + 7 * 32));
                s += __expf(a0.x + b0.x) + __expf(a0.y + b0.y)
                   + __expf(a0.z + b0.z) + __expf(a0.w + b0.w);
                s += __expf(a1.x + b1.x) + __expf(a1.y + b1.y)
                   + __expf(a1.z + b1.z) + __expf(a1.w + b1.w);
                s += __expf(a2.x + b2.x) + __expf(a2.y + b2.y)
                   + __expf(a2.z + b2.z) + __expf(a2.w + b2.w);
                s += __expf(a3.x + b3.x) + __expf(a3.y + b3.y)
                   + __expf(a3.z + b3.z) + __expf(a3.w + b3.w);
            }

            // Reduce within the 8-lane group: 3 shuffle levels for 4 columns.
            #pragma unroll
            for (int off = 4; off > 0; off >>= 1)
                s += __shfl_xor_sync(0xFFFFFFFFu, s, off);

            if (sub == 0 && !mk)
                acc += (__logf(s) - zt);   // -(z_t - lse)
        }
    }

    // One block reduce at the very end (not per row).
    #pragma unroll
    for (int off = 16; off > 0; off >>= 1)
        acc += __shfl_xor_sync(0xFFFFFFFFu, acc, off);

    __shared__ float sacc[8];
    __shared__ bool  s_last;
    if (lane == 0) sacc[wid] = acc;
    __syncthreads();

    if (threadIdx.x == 0) {
        float s = 0.0f;
        #pragma unroll
        for (int i = 0; i < 8; ++i) s += sacc[i];
        g_block_partials[blockIdx.x] = s;
        __threadfence();                                   // publish partial
        unsigned int t = atomicAdd(&g_ticket, 1u);
        s_last = (t == (unsigned int)(GRID - 1));
    }
    __syncthreads();

    // Last block performs the final deterministic reduction over 592 partials.
    if (s_last) {
        float s = 0.0f;
        for (int i = threadIdx.x; i < GRID; i += 256)
            s += g_block_partials[i];
        #pragma unroll
        for (int off = 16; off > 0; off >>= 1)
            s += __shfl_xor_sync(0xFFFFFFFFu, s, off);
        if (lane == 0) sacc[wid] = s;
        __syncthreads();
        if (threadIdx.x == 0) {
            float loss = 0.0f;
            #pragma unroll
            for (int i = 0; i < 8; ++i) loss += sacc[i];
            out[0] = loss;
            out[1] = loss / ((float)B_ROWS * 0.69314718055994530942f);
            g_ticket = 0;                                  // reset for next replay
        }
    }
}

extern "C" void kernel_launch(void* const* d_in, const int* in_sizes, int n_in,
                              void* d_out, int out_size)
{
    const float* logits  = (const float*)d_in[0];
    const float* gumbel  = (const float*)d_in[1];
    const int*   mask    = (const int*)d_in[2];
    const int*   targets = (const int*)d_in[3];
    // d_in[4] = bin_size scalar (256), fixed — unused.
    (void)in_sizes; (void)n_in; (void)out_size;

    obs_loss_kernel<<<GRID, 256>>>(logits, gumbel, mask, targets, (float*)d_out);
}

// round 13
// speedup vs baseline: 1.2548x; 1.1564x over previous
#include <cuda_runtime.h>
#include <cuda_bf16.h>

// Problem constants (fixed shapes per reference)
#define B_ROWS   4096
#define N_COLS   64
#define BIN      256
#define TOT      (N_COLS * BIN)   // 16384

// Persistent grid: 3 CTAs/SM on 148 SMs (85-reg budget -> 16-deep batches).
#define GRID     444

// Scratch: per-block partials + last-block ticket counter (no allocs allowed).
__device__ float g_block_partials[GRID];
__device__ unsigned int g_ticket = 0;   // reset to 0 by the last block each launch

// Persistent kernel, lean body + max-depth batching. Warp = 4 columns per
// iteration via 8-lane groups (grp = lane>>3 selects the column, sub = lane&7
// covers bins sub*4 + k*32). ALL 16 LDG.128 of an iteration are issued as a
// single front batch (8KB/warp in flight); nothing from z is retained -- the
// target bin's z is re-loaded by the group leader. Reduction is 3 shfl levels
// for 4 columns. No max-subtraction: z bounded (logits ~N(0,1),
// gumbel <= ~23), fp32-safe.
__global__ __launch_bounds__(256, 3)
void obs_loss_kernel(const float* __restrict__ logits,
                     const float* __restrict__ gumbel,
                     const int* __restrict__ mask,      // jax bool -> int32
                     const int* __restrict__ targets,
                     float* __restrict__ out)
{
    const int wid  = threadIdx.x >> 5;
    const int lane = threadIdx.x & 31;
    const int grp  = lane >> 3;    // which of the warp's 4 columns
    const int sub  = lane & 7;     // position within the 8-lane group

    float acc = 0.0f;   // accumulated across all rows this block handles

    for (int row = blockIdx.x; row < B_ROWS; row += GRID) {
        const float* lrow = logits + (size_t)row * TOT;
        const float* grow = gumbel + (size_t)row * TOT;

        #pragma unroll
        for (int it = 0; it < 2; ++it) {
            const int mycol = it * 32 + wid * 4 + grp;
            const int cbase = mycol * BIN;

            // Group leader prefetches the scattered tail data early so the
            // latency overlaps the streaming loads below.
            int   t_idx = 0, mk = 1;
            float zt = 0.0f;
            if (sub == 0) {
                t_idx = __ldg(&targets[row * N_COLS + mycol]);
                mk    = __ldg(&mask[(size_t)row * TOT + cbase + t_idx]);
                zt    = __ldg(lrow + cbase + t_idx) + __ldg(grow + cbase + t_idx);
            }

            const float* lp = lrow + cbase + sub * 4;
            const float* gp = grow + cbase + sub * 4;

            // ---- Single 16-deep front batch: 8KB per warp in flight.
            float4 a0 = __ldcs(reinterpret_cast<const float4*>(lp + 0 * 32));
            float4 a1 = __ldcs(reinterpret_cast<const float4*>(lp + 1 * 32));
            float4 a2 = __ldcs(reinterpret_cast<const float4*>(lp + 2 * 32));
            float4 a3 = __ldcs(reinterpret_cast<const float4*>(lp + 3 * 32));
            float4 a4 = __ldcs(reinterpret_cast<const float4*>(lp + 4 * 32));
            float4 a5 = __ldcs(reinterpret_cast<const float4*>(lp + 5 * 32));
            float4 a6 = __ldcs(reinterpret_cast<const float4*>(lp + 6 * 32));
            float4 a7 = __ldcs(reinterpret_cast<const float4*>(lp + 7 * 32));
            float4 b0 = __ldcs(reinterpret_cast<const float4*>(gp + 0 * 32));
            float4 b1 = __ldcs(reinterpret_cast<const float4*>(gp + 1 * 32));
            float4 b2 = __ldcs(reinterpret_cast<const float4*>(gp + 2 * 32));
            float4 b3 = __ldcs(reinterpret_cast<const float4*>(gp + 3 * 32));
            float4 b4 = __ldcs(reinterpret_cast<const float4*>(gp + 4 * 32));
            float4 b5 = __ldcs(reinterpret_cast<const float4*>(gp + 5 * 32));
            float4 b6 = __ldcs(reinterpret_cast<const float4*>(gp + 6 * 32));
            float4 b7 = __ldcs(reinterpret_cast<const float4*>(gp + 7 * 32));

            float s;
            s  = __expf(a0.x + b0.x) + __expf(a0.y + b0.y)
               + __expf(a0.z + b0.z) + __expf(a0.w + b0.w);
            s += __expf(a1.x + b1.x) + __expf(a1.y + b1.y)
               + __expf(a1.z + b1.z) + __expf(a1.w + b1.w);
            s += __expf(a2.x + b2.x) + __expf(a2.y + b2.y)
               + __expf(a2.z + b2.z) + __expf(a2.w + b2.w);
            s += __expf(a3.x + b3.x) + __expf(a3.y + b3.y)
               + __expf(a3.z + b3.z) + __expf(a3.w + b3.w);
            s += __expf(a4.x + b4.x) + __expf(a4.y + b4.y)
               + __expf(a4.z + b4.z) + __expf(a4.w + b4.w);
            s += __expf(a5.x + b5.x) + __expf(a5.y + b5.y)
               + __expf(a5.z + b5.z) + __expf(a5.w + b5.w);
            s += __expf(a6.x + b6.x) + __expf(a6.y + b6.y)
               + __expf(a6.z + b6.z) + __expf(a6.w + b6.w);
            s += __expf(a7.x + b7.x) + __expf(a7.y + b7.y)
               + __expf(a7.z + b7.z) + __expf(a7.w + b7.w);

            // Reduce within the 8-lane group: 3 shuffle levels for 4 columns.
            #pragma unroll
            for (int off = 4; off > 0; off >>= 1)
                s += __shfl_xor_sync(0xFFFFFFFFu, s, off);

            if (sub == 0 && !mk)
                acc += (__logf(s) - zt);   // -(z_t - lse)
        }
    }

    // One block reduce at the very end (not per row).
    #pragma unroll
    for (int off = 16; off > 0; off >>= 1)
        acc += __shfl_xor_sync(0xFFFFFFFFu, acc, off);

    __shared__ float sacc[8];
    __shared__ bool  s_last;
    if (lane == 0) sacc[wid] = acc;
    __syncthreads();

    if (threadIdx.x == 0) {
        float s = 0.0f;
        #pragma unroll
        for (int i = 0; i < 8; ++i) s += sacc[i];
        g_block_partials[blockIdx.x] = s;
        __threadfence();                                   // publish partial
        unsigned int t = atomicAdd(&g_ticket, 1u);
        s_last = (t == (unsigned int)(GRID - 1));
    }
    __syncthreads();

    // Last block performs the final deterministic reduction over 444 partials.
    if (s_last) {
        float s = 0.0f;
        for (int i = threadIdx.x; i < GRID; i += 256)
            s += g_block_partials[i];
        #pragma unroll
        for (int off = 16; off > 0; off >>= 1)
            s += __shfl_xor_sync(0xFFFFFFFFu, s, off);
        if (lane == 0) sacc[wid] = s;
        __syncthreads();
        if (threadIdx.x == 0) {
            float loss = 0.0f;
            #pragma unroll
            for (int i = 0; i < 8; ++i) loss += sacc[i];
            out[0] = loss;
            out[1] = loss / ((float)B_ROWS * 0.69314718055994530942f);
            g_ticket = 0;                                  // reset for next replay
        }
    }
}

extern "C" void kernel_launch(void* const* d_in, const int* in_sizes, int n_in,
                              void* d_out, int out_size)
{
    const float* logits  = (const float*)d_in[0];
    const float* gumbel  = (const float*)d_in[1];
    const int*   mask    = (const int*)d_in[2];
    const int*   targets = (const int*)d_in[3];
    // d_in[4] = bin_size scalar (256), fixed — unused.
    (void)in_sizes; (void)n_in; (void)out_size;

    obs_loss_kernel<<<GRID, 256>>>(logits, gumbel, mask, targets, (float*)d_out);
}